// round 1
// baseline (speedup 1.0000x reference)
#include <cuda_runtime.h>
#include <cuda_bf16.h>

// Problem constants
#define Bb 2048
#define Tt 2048
// F=8, U=3, 3U=9

// Scratch: zero-init __device__ globals (allocation-free rule)
__device__ float4 g_bufZ[(size_t)Tt * Bb];  // {xz0,xz1,xz2, mask}
__device__ float4 g_bufR[(size_t)Tt * Bb];  // {xr0,xr1,xr2, 0}
__device__ float4 g_bufH[(size_t)Tt * Bb];  // {xh0,xh1,xh2, 0}
__device__ float  g_outT[(size_t)Tt * Bb];  // out in [t][b] layout

__device__ __forceinline__ float fast_rcp(float a) {
    float r;
    asm("rcp.approx.f32 %0, %1;" : "=f"(r) : "f"(a));
    return r;
}

// sigmoid(x) = 1 / (1 + exp(-x)) : EX2 + RCP, ~1e-7 accurate on our range
__device__ __forceinline__ float sigm(float x) {
    float e = __expf(-x);
    return fast_rcp(1.0f + e);
}

// tanh(x) = (1 - e) / (1 + e), e = exp(-2x)
__device__ __forceinline__ float tanh_acc(float x) {
    float e = __expf(-2.0f * x);
    return (1.0f - e) * fast_rcp(1.0f + e);
}

// ---------------------------------------------------------------------------
// Kernel A: input projection + mask, writes [t][b]-major packed tiles.
// grid (8, 256), block 256. Each thread: one b, 8 consecutive t.
// ---------------------------------------------------------------------------
__global__ void __launch_bounds__(256) prep_kernel(
    const float* __restrict__ x,       // [B][T][8]
    const float* __restrict__ kern,    // [8][9]
    const float* __restrict__ bias_i,  // [9]
    const float* __restrict__ bias_r)  // [9]
{
    const int b  = blockIdx.x * 256 + threadIdx.x;
    const int t0 = blockIdx.y * 8;

    float bs[9];
#pragma unroll
    for (int j = 0; j < 9; j++) bs[j] = __ldg(bias_i + j) + __ldg(bias_r + j);
    float wv[8][9];
#pragma unroll
    for (int f = 0; f < 8; f++)
#pragma unroll
        for (int j = 0; j < 9; j++) wv[f][j] = __ldg(kern + f * 9 + j);

    const float4* x4 = reinterpret_cast<const float4*>(x) + (size_t)b * (Tt * 2);

#pragma unroll
    for (int i = 0; i < 8; i++) {
        const int t = t0 + i;
        float4 a = __ldg(x4 + (size_t)t * 2);
        float4 c = __ldg(x4 + (size_t)t * 2 + 1);
        float xf[8] = {a.x, a.y, a.z, a.w, c.x, c.y, c.z, c.w};

        float m = 0.0f;
#pragma unroll
        for (int f = 0; f < 8; f++)
            if (xf[f] != 0.0f) m = 1.0f;

        float acc[9];
#pragma unroll
        for (int j = 0; j < 9; j++) {
            float s = bs[j];
#pragma unroll
            for (int f = 0; f < 8; f++) s = fmaf(xf[f], wv[f][j], s);
            acc[j] = s;
        }

        const size_t o = (size_t)t * Bb + b;
        g_bufZ[o] = make_float4(acc[0], acc[1], acc[2], m);
        g_bufR[o] = make_float4(acc[3], acc[4], acc[5], 0.0f);
        g_bufH[o] = make_float4(acc[6], acc[7], acc[8], 0.0f);
    }
}

// ---------------------------------------------------------------------------
// Kernel B: sequential GRU scan. 64 blocks x 32 threads = 2048 lanes, one per
// batch row. 1 warp per SM -> latency/issue bound; keep the loop body minimal
// and software-pipeline the xw loads (depth 4).
// ---------------------------------------------------------------------------
__global__ void __launch_bounds__(32) scan_kernel(
    const float* __restrict__ rk,       // [3][9]
    const float* __restrict__ dense_w,  // [3][1]
    const float* __restrict__ dense_b)  // [1]
{
    const int b = blockIdx.x * 32 + threadIdx.x;

    float rkv[3][9];
#pragma unroll
    for (int u = 0; u < 3; u++)
#pragma unroll
        for (int j = 0; j < 9; j++) rkv[u][j] = __ldg(rk + u * 9 + j);

    const float w0 = __ldg(dense_w);
    const float w1 = __ldg(dense_w + 1);
    const float w2 = __ldg(dense_w + 2);
    const float db = __ldg(dense_b);

    float h0 = 0.0f, h1 = 0.0f, h2 = 0.0f;

    // prefetch pipeline, depth 4
    float4 pz[4], pr[4], ph[4];
#pragma unroll
    for (int d = 0; d < 4; d++) {
        const size_t o = (size_t)d * Bb + b;
        pz[d] = __ldg(&g_bufZ[o]);
        pr[d] = __ldg(&g_bufR[o]);
        ph[d] = __ldg(&g_bufH[o]);
    }

    for (int t = 0; t < Tt; t += 4) {
#pragma unroll
        for (int i = 0; i < 4; i++) {
            const float4 vz = pz[i];
            const float4 vr = pr[i];
            const float4 vh = ph[i];

            const int tp = t + i + 4;
            if (tp < Tt) {
                const size_t o = (size_t)tp * Bb + b;
                pz[i] = __ldg(&g_bufZ[o]);
                pr[i] = __ldg(&g_bufR[o]);
                ph[i] = __ldg(&g_bufH[o]);
            }

            // hw = h @ recurrent_kernel (bias_r already folded into xw)
            float hz0 = fmaf(h2, rkv[2][0], fmaf(h1, rkv[1][0], h0 * rkv[0][0]));
            float hz1 = fmaf(h2, rkv[2][1], fmaf(h1, rkv[1][1], h0 * rkv[0][1]));
            float hz2 = fmaf(h2, rkv[2][2], fmaf(h1, rkv[1][2], h0 * rkv[0][2]));
            float hr0 = fmaf(h2, rkv[2][3], fmaf(h1, rkv[1][3], h0 * rkv[0][3]));
            float hr1 = fmaf(h2, rkv[2][4], fmaf(h1, rkv[1][4], h0 * rkv[0][4]));
            float hr2 = fmaf(h2, rkv[2][5], fmaf(h1, rkv[1][5], h0 * rkv[0][5]));
            float hh0 = fmaf(h2, rkv[2][6], fmaf(h1, rkv[1][6], h0 * rkv[0][6]));
            float hh1 = fmaf(h2, rkv[2][7], fmaf(h1, rkv[1][7], h0 * rkv[0][7]));
            float hh2 = fmaf(h2, rkv[2][8], fmaf(h1, rkv[1][8], h0 * rkv[0][8]));

            const float z0 = sigm(vz.x + hz0);
            const float z1 = sigm(vz.y + hz1);
            const float z2 = sigm(vz.z + hz2);
            const float r0 = sigm(vr.x + hr0);
            const float r1 = sigm(vr.y + hr1);
            const float r2 = sigm(vr.z + hr2);

            const float hc0 = tanh_acc(fmaf(r0, hh0, vh.x));
            const float hc1 = tanh_acc(fmaf(r1, hh1, vh.y));
            const float hc2 = tanh_acc(fmaf(r2, hh2, vh.z));

            // h_new_full = z*h + (1-z)*hc  ==  hc + z*(h - hc)
            const float hn0 = fmaf(z0, h0 - hc0, hc0);
            const float hn1 = fmaf(z1, h1 - hc1, hc1);
            const float hn2 = fmaf(z2, h2 - hc2, hc2);

            const float m = vz.w;  // 0 or 1

            // out = where(m, hn, 0) @ w + db = m * (hn . w) + db
            const float dot = fmaf(hn2, w2, fmaf(hn1, w1, hn0 * w0));
            g_outT[(size_t)(t + i) * Bb + b] = fmaf(m, dot, db);

            // h = where(m, hn, h) = h + m*(hn - h)
            h0 = fmaf(m, hn0 - h0, h0);
            h1 = fmaf(m, hn1 - h1, h1);
            h2 = fmaf(m, hn2 - h2, h2);
        }
    }
}

// ---------------------------------------------------------------------------
// Kernel C: transpose g_outT[t][b] -> out[b][t]
// ---------------------------------------------------------------------------
__global__ void transpose_kernel(float* __restrict__ out) {
    __shared__ float tile[32][33];
    const int bBase = blockIdx.x * 32;
    const int tBase = blockIdx.y * 32;

    tile[threadIdx.y][threadIdx.x] =
        g_outT[(size_t)(tBase + threadIdx.y) * Bb + (bBase + threadIdx.x)];
    __syncthreads();
    out[(size_t)(bBase + threadIdx.y) * Tt + (tBase + threadIdx.x)] =
        tile[threadIdx.x][threadIdx.y];
}

// ---------------------------------------------------------------------------
extern "C" void kernel_launch(void* const* d_in, const int* in_sizes, int n_in,
                              void* d_out, int out_size) {
    const float* x       = (const float*)d_in[0];  // (B,T,8)
    const float* kern    = (const float*)d_in[1];  // (8,9)
    const float* rk      = (const float*)d_in[2];  // (3,9)
    const float* bias_i  = (const float*)d_in[3];  // (9,)
    const float* bias_r  = (const float*)d_in[4];  // (9,)
    const float* dense_w = (const float*)d_in[5];  // (3,1)
    const float* dense_b = (const float*)d_in[6];  // (1,)
    float* out = (float*)d_out;                    // (B,T,1)

    (void)in_sizes; (void)n_in; (void)out_size;

    dim3 gA(Bb / 256, Tt / 8);
    prep_kernel<<<gA, 256>>>(x, kern, bias_i, bias_r);

    scan_kernel<<<Bb / 32, 32>>>(rk, dense_w, dense_b);

    dim3 gC(Bb / 32, Tt / 32);
    transpose_kernel<<<gC, dim3(32, 32)>>>(out);
}

// round 3
// speedup vs baseline: 1.5830x; 1.5830x over previous
#include <cuda_runtime.h>
#include <cuda_bf16.h>

// Problem constants
#define Bb 2048
#define Tt 2048
// F=8, U=3, 3U=9

// Scratch: __device__ globals (allocation-free rule)
__device__ float4 g_bufZ[(size_t)Tt * Bb];  // {0.5*xz0, 0.5*xz1, 0.5*xz2, mask}
__device__ float4 g_bufR[(size_t)Tt * Bb];  // {0.5*xr0, 0.5*xr1, 0.5*xr2, 0}
__device__ float4 g_bufH[(size_t)Tt * Bb];  // {xh0, xh1, xh2, 0}
__device__ float  g_outT[(size_t)Tt * Bb];  // out in [t][b] layout

// HW tanh (sm_75+): 1 MUFU op, rel err ~2^-11
__device__ __forceinline__ float tanh_fast(float x) {
    float y;
    asm("tanh.approx.f32 %0, %1;" : "=f"(y) : "f"(x));
    return y;
}

// ---------------------------------------------------------------------------
// Kernel A: input projection + mask, writes [t][b]-major packed tiles.
// z/r pre-activations stored PRE-HALVED so the scan's sigmoid-via-tanh
// needs no extra scaling ops.
// ---------------------------------------------------------------------------
__global__ void __launch_bounds__(256) prep_kernel(
    const float* __restrict__ x,       // [B][T][8]
    const float* __restrict__ kern,    // [8][9]
    const float* __restrict__ bias_i,  // [9]
    const float* __restrict__ bias_r)  // [9]
{
    const int b  = blockIdx.x * 256 + threadIdx.x;
    const int t0 = blockIdx.y * 8;

    float bs[9];
#pragma unroll
    for (int j = 0; j < 9; j++) bs[j] = __ldg(bias_i + j) + __ldg(bias_r + j);
    float wv[8][9];
#pragma unroll
    for (int f = 0; f < 8; f++)
#pragma unroll
        for (int j = 0; j < 9; j++) wv[f][j] = __ldg(kern + f * 9 + j);

    const float4* x4 = reinterpret_cast<const float4*>(x) + (size_t)b * (Tt * 2);

#pragma unroll
    for (int i = 0; i < 8; i++) {
        const int t = t0 + i;
        float4 a = __ldg(x4 + (size_t)t * 2);
        float4 c = __ldg(x4 + (size_t)t * 2 + 1);
        float xf[8] = {a.x, a.y, a.z, a.w, c.x, c.y, c.z, c.w};

        float m = 0.0f;
#pragma unroll
        for (int f = 0; f < 8; f++)
            if (xf[f] != 0.0f) m = 1.0f;

        float acc[9];
#pragma unroll
        for (int j = 0; j < 9; j++) {
            float s = bs[j];
#pragma unroll
            for (int f = 0; f < 8; f++) s = fmaf(xf[f], wv[f][j], s);
            acc[j] = s;
        }

        const size_t o = (size_t)t * Bb + b;
        g_bufZ[o] = make_float4(0.5f * acc[0], 0.5f * acc[1], 0.5f * acc[2], m);
        g_bufR[o] = make_float4(0.5f * acc[3], 0.5f * acc[4], 0.5f * acc[5], 0.0f);
        g_bufH[o] = make_float4(acc[6], acc[7], acc[8], 0.0f);
    }
}

// ---------------------------------------------------------------------------
// Kernel B: sequential GRU scan. 64 blocks x 32 threads = 2048 lanes (one per
// batch row). Memory structure IDENTICAL to the R1 kernel that passed
// (prefetch depth 4, same predication); only gate math changed:
// gates via tanh.approx -> 9 MUFU/step (was 18 EX2/RCP pairs).
// ---------------------------------------------------------------------------
__global__ void __launch_bounds__(32) scan_kernel(
    const float* __restrict__ rk,       // [3][9]
    const float* __restrict__ dense_w,  // [3][1]
    const float* __restrict__ dense_b)  // [1]
{
    const int b = blockIdx.x * 32 + threadIdx.x;

    // z/r columns (0..5) pre-halved to match pre-halved xz/xr.
    float rkv[3][9];
#pragma unroll
    for (int u = 0; u < 3; u++)
#pragma unroll
        for (int j = 0; j < 9; j++) {
            float v = __ldg(rk + u * 9 + j);
            rkv[u][j] = (j < 6) ? 0.5f * v : v;
        }

    const float w0 = __ldg(dense_w);
    const float w1 = __ldg(dense_w + 1);
    const float w2 = __ldg(dense_w + 2);
    const float db = __ldg(dense_b);

    float h0 = 0.0f, h1 = 0.0f, h2 = 0.0f;

    // prefetch pipeline, depth 4 (exact R1 structure)
    float4 pz[4], pr[4], ph[4];
#pragma unroll
    for (int d = 0; d < 4; d++) {
        const size_t o = (size_t)d * Bb + b;
        pz[d] = __ldg(&g_bufZ[o]);
        pr[d] = __ldg(&g_bufR[o]);
        ph[d] = __ldg(&g_bufH[o]);
    }

    for (int t = 0; t < Tt; t += 4) {
#pragma unroll
        for (int i = 0; i < 4; i++) {
            const float4 vz = pz[i];
            const float4 vr = pr[i];
            const float4 vh = ph[i];

            const int tp = t + i + 4;
            if (tp < Tt) {
                const size_t o = (size_t)tp * Bb + b;
                pz[i] = __ldg(&g_bufZ[o]);
                pr[i] = __ldg(&g_bufR[o]);
                ph[i] = __ldg(&g_bufH[o]);
            }

            // hw = h @ recurrent_kernel  (z/r cols pre-halved; biases folded)
            float hz0 = fmaf(h2, rkv[2][0], fmaf(h1, rkv[1][0], h0 * rkv[0][0]));
            float hz1 = fmaf(h2, rkv[2][1], fmaf(h1, rkv[1][1], h0 * rkv[0][1]));
            float hz2 = fmaf(h2, rkv[2][2], fmaf(h1, rkv[1][2], h0 * rkv[0][2]));
            float hr0 = fmaf(h2, rkv[2][3], fmaf(h1, rkv[1][3], h0 * rkv[0][3]));
            float hr1 = fmaf(h2, rkv[2][4], fmaf(h1, rkv[1][4], h0 * rkv[0][4]));
            float hr2 = fmaf(h2, rkv[2][5], fmaf(h1, rkv[1][5], h0 * rkv[0][5]));
            float hh0 = fmaf(h2, rkv[2][6], fmaf(h1, rkv[1][6], h0 * rkv[0][6]));
            float hh1 = fmaf(h2, rkv[2][7], fmaf(h1, rkv[1][7], h0 * rkv[0][7]));
            float hh2 = fmaf(h2, rkv[2][8], fmaf(h1, rkv[1][8], h0 * rkv[0][8]));

            // sigmoid(x) = 0.5 + 0.5*tanh(x/2); args already halved
            const float z0 = fmaf(tanh_fast(vz.x + hz0), 0.5f, 0.5f);
            const float z1 = fmaf(tanh_fast(vz.y + hz1), 0.5f, 0.5f);
            const float z2 = fmaf(tanh_fast(vz.z + hz2), 0.5f, 0.5f);
            const float r0 = fmaf(tanh_fast(vr.x + hr0), 0.5f, 0.5f);
            const float r1 = fmaf(tanh_fast(vr.y + hr1), 0.5f, 0.5f);
            const float r2 = fmaf(tanh_fast(vr.z + hr2), 0.5f, 0.5f);

            const float hc0 = tanh_fast(fmaf(r0, hh0, vh.x));
            const float hc1 = tanh_fast(fmaf(r1, hh1, vh.y));
            const float hc2 = tanh_fast(fmaf(r2, hh2, vh.z));

            // h_new_full = z*h + (1-z)*hc == hc + z*(h - hc)
            const float hn0 = fmaf(z0, h0 - hc0, hc0);
            const float hn1 = fmaf(z1, h1 - hc1, hc1);
            const float hn2 = fmaf(z2, h2 - hc2, hc2);

            const float m = vz.w;  // 0 or 1

            // out = m * (hn . w) + db
            const float dot = fmaf(hn2, w2, fmaf(hn1, w1, hn0 * w0));
            g_outT[(size_t)(t + i) * Bb + b] = fmaf(m, dot, db);

            // h = h + m*(hn - h)
            h0 = fmaf(m, hn0 - h0, h0);
            h1 = fmaf(m, hn1 - h1, h1);
            h2 = fmaf(m, hn2 - h2, h2);
        }
    }
}

// ---------------------------------------------------------------------------
// Kernel C: transpose g_outT[t][b] -> out[b][t]
// ---------------------------------------------------------------------------
__global__ void transpose_kernel(float* __restrict__ out) {
    __shared__ float tile[32][33];
    const int bBase = blockIdx.x * 32;
    const int tBase = blockIdx.y * 32;

    tile[threadIdx.y][threadIdx.x] =
        g_outT[(size_t)(tBase + threadIdx.y) * Bb + (bBase + threadIdx.x)];
    __syncthreads();
    out[(size_t)(bBase + threadIdx.y) * Tt + (tBase + threadIdx.x)] =
        tile[threadIdx.x][threadIdx.y];
}

// ---------------------------------------------------------------------------
extern "C" void kernel_launch(void* const* d_in, const int* in_sizes, int n_in,
                              void* d_out, int out_size) {
    const float* x       = (const float*)d_in[0];  // (B,T,8)
    const float* kern    = (const float*)d_in[1];  // (8,9)
    const float* rk      = (const float*)d_in[2];  // (3,9)
    const float* bias_i  = (const float*)d_in[3];  // (9,)
    const float* bias_r  = (const float*)d_in[4];  // (9,)
    const float* dense_w = (const float*)d_in[5];  // (3,1)
    const float* dense_b = (const float*)d_in[6];  // (1,)
    float* out = (float*)d_out;                    // (B,T,1)

    (void)in_sizes; (void)n_in; (void)out_size;

    dim3 gA(Bb / 256, Tt / 8);
    prep_kernel<<<gA, 256>>>(x, kern, bias_i, bias_r);

    scan_kernel<<<Bb / 32, 32>>>(rk, dense_w, dense_b);

    dim3 gC(Bb / 32, Tt / 32);
    transpose_kernel<<<gC, dim3(32, 32)>>>(out);
}

// round 4
// speedup vs baseline: 2.0565x; 1.2991x over previous
#include <cuda_runtime.h>
#include <cuda_bf16.h>

// Problem constants
#define Bb 2048
#define Tt 2048
#define PF 8   // prefetch pipeline depth (buffers padded by PF steps)
// F=8, U=3, 3U=9

// Scratch: __device__ globals (allocation-free rule). Padded by PF steps so
// ALL prefetch loads in the scan are unconditional and in-bounds.
__device__ float4 g_bufZ[(size_t)(Tt + PF) * Bb];  // {.5*xz0,.5*xz1,.5*xz2, mask}
__device__ float4 g_bufR[(size_t)(Tt + PF) * Bb];  // {.5*xr0,.5*xr1,.5*xr2, 0}
__device__ float4 g_bufH[(size_t)(Tt + PF) * Bb];  // {xh0, xh1, xh2, 0}
__device__ float  g_outT[(size_t)Tt * Bb];         // out in [t][b] layout

// HW tanh (sm_75+): 1 MUFU op, rel err ~2^-11
__device__ __forceinline__ float tanh_fast(float x) {
    float y;
    asm("tanh.approx.f32 %0, %1;" : "=f"(y) : "f"(x));
    return y;
}

// ---------------------------------------------------------------------------
// Kernel A: input projection + mask -> [t][b]-major packed tiles.
// z/r pre-activations stored PRE-HALVED (sigmoid-via-tanh needs x/2).
// ---------------------------------------------------------------------------
__global__ void __launch_bounds__(256) prep_kernel(
    const float* __restrict__ x,       // [B][T][8]
    const float* __restrict__ kern,    // [8][9]
    const float* __restrict__ bias_i,  // [9]
    const float* __restrict__ bias_r)  // [9]
{
    const int b  = blockIdx.x * 256 + threadIdx.x;
    const int t0 = blockIdx.y * 8;

    float bs[9];
#pragma unroll
    for (int j = 0; j < 9; j++) bs[j] = __ldg(bias_i + j) + __ldg(bias_r + j);
    float wv[8][9];
#pragma unroll
    for (int f = 0; f < 8; f++)
#pragma unroll
        for (int j = 0; j < 9; j++) wv[f][j] = __ldg(kern + f * 9 + j);

    const float4* x4 = reinterpret_cast<const float4*>(x) + (size_t)b * (Tt * 2);

#pragma unroll
    for (int i = 0; i < 8; i++) {
        const int t = t0 + i;
        float4 a = __ldg(x4 + (size_t)t * 2);
        float4 c = __ldg(x4 + (size_t)t * 2 + 1);
        float xf[8] = {a.x, a.y, a.z, a.w, c.x, c.y, c.z, c.w};

        float m = 0.0f;
#pragma unroll
        for (int f = 0; f < 8; f++)
            if (xf[f] != 0.0f) m = 1.0f;

        float acc[9];
#pragma unroll
        for (int j = 0; j < 9; j++) {
            float s = bs[j];
#pragma unroll
            for (int f = 0; f < 8; f++) s = fmaf(xf[f], wv[f][j], s);
            acc[j] = s;
        }

        const size_t o = (size_t)t * Bb + b;
        g_bufZ[o] = make_float4(0.5f * acc[0], 0.5f * acc[1], 0.5f * acc[2], m);
        g_bufR[o] = make_float4(0.5f * acc[3], 0.5f * acc[4], 0.5f * acc[5], 0.0f);
        g_bufH[o] = make_float4(acc[6], acc[7], acc[8], 0.0f);
    }
}

// ---------------------------------------------------------------------------
// Kernel B: sequential GRU scan, 64 blocks x 32 threads = 2048 lanes.
// Prefetch pipeline depth PF=8 with UNCONDITIONAL loads (buffers padded),
// so ptxas can front-batch the LDGs and the full 8-step latency coverage
// is structurally guaranteed.
// ---------------------------------------------------------------------------
__global__ void __launch_bounds__(32) scan_kernel(
    const float* __restrict__ rk,       // [3][9]
    const float* __restrict__ dense_w,  // [3][1]
    const float* __restrict__ dense_b)  // [1]
{
    const int b = blockIdx.x * 32 + threadIdx.x;

    // z/r columns (0..5) pre-halved to match pre-halved xz/xr.
    float rkv[3][9];
#pragma unroll
    for (int u = 0; u < 3; u++)
#pragma unroll
        for (int j = 0; j < 9; j++) {
            float v = __ldg(rk + u * 9 + j);
            rkv[u][j] = (j < 6) ? 0.5f * v : v;
        }

    const float w0 = __ldg(dense_w);
    const float w1 = __ldg(dense_w + 1);
    const float w2 = __ldg(dense_w + 2);
    const float db = __ldg(dense_b);

    float h0 = 0.0f, h1 = 0.0f, h2 = 0.0f;

    // prime the pipeline
    float4 pz[PF], pr[PF], ph[PF];
#pragma unroll
    for (int d = 0; d < PF; d++) {
        const size_t o = (size_t)d * Bb + b;
        pz[d] = __ldg(&g_bufZ[o]);
        pr[d] = __ldg(&g_bufR[o]);
        ph[d] = __ldg(&g_bufH[o]);
    }

    for (int t = 0; t < Tt; t += PF) {
#pragma unroll
        for (int i = 0; i < PF; i++) {
            const float4 vz = pz[i];
            const float4 vr = pr[i];
            const float4 vh = ph[i];

            // unconditional prefetch PF steps ahead (padded region covers tail)
            {
                const size_t o = (size_t)(t + i + PF) * Bb + b;
                pz[i] = __ldg(&g_bufZ[o]);
                pr[i] = __ldg(&g_bufR[o]);
                ph[i] = __ldg(&g_bufH[o]);
            }

            // hw = h @ recurrent_kernel  (z/r cols pre-halved; biases folded)
            float hz0 = fmaf(h2, rkv[2][0], fmaf(h1, rkv[1][0], h0 * rkv[0][0]));
            float hz1 = fmaf(h2, rkv[2][1], fmaf(h1, rkv[1][1], h0 * rkv[0][1]));
            float hz2 = fmaf(h2, rkv[2][2], fmaf(h1, rkv[1][2], h0 * rkv[0][2]));
            float hr0 = fmaf(h2, rkv[2][3], fmaf(h1, rkv[1][3], h0 * rkv[0][3]));
            float hr1 = fmaf(h2, rkv[2][4], fmaf(h1, rkv[1][4], h0 * rkv[0][4]));
            float hr2 = fmaf(h2, rkv[2][5], fmaf(h1, rkv[1][5], h0 * rkv[0][5]));
            float hh0 = fmaf(h2, rkv[2][6], fmaf(h1, rkv[1][6], h0 * rkv[0][6]));
            float hh1 = fmaf(h2, rkv[2][7], fmaf(h1, rkv[1][7], h0 * rkv[0][7]));
            float hh2 = fmaf(h2, rkv[2][8], fmaf(h1, rkv[1][8], h0 * rkv[0][8]));

            // sigmoid(x) = 0.5 + 0.5*tanh(x/2); args already halved
            const float z0 = fmaf(tanh_fast(vz.x + hz0), 0.5f, 0.5f);
            const float z1 = fmaf(tanh_fast(vz.y + hz1), 0.5f, 0.5f);
            const float z2 = fmaf(tanh_fast(vz.z + hz2), 0.5f, 0.5f);
            const float r0 = fmaf(tanh_fast(vr.x + hr0), 0.5f, 0.5f);
            const float r1 = fmaf(tanh_fast(vr.y + hr1), 0.5f, 0.5f);
            const float r2 = fmaf(tanh_fast(vr.z + hr2), 0.5f, 0.5f);

            const float hc0 = tanh_fast(fmaf(r0, hh0, vh.x));
            const float hc1 = tanh_fast(fmaf(r1, hh1, vh.y));
            const float hc2 = tanh_fast(fmaf(r2, hh2, vh.z));

            // h_new_full = z*h + (1-z)*hc == hc + z*(h - hc)
            const float hn0 = fmaf(z0, h0 - hc0, hc0);
            const float hn1 = fmaf(z1, h1 - hc1, hc1);
            const float hn2 = fmaf(z2, h2 - hc2, hc2);

            const float m = vz.w;  // 0 or 1

            // out = m * (hn . w) + db
            const float dot = fmaf(hn2, w2, fmaf(hn1, w1, hn0 * w0));
            g_outT[(size_t)(t + i) * Bb + b] = fmaf(m, dot, db);

            // h = h + m*(hn - h)
            h0 = fmaf(m, hn0 - h0, h0);
            h1 = fmaf(m, hn1 - h1, h1);
            h2 = fmaf(m, hn2 - h2, h2);
        }
    }
}

// ---------------------------------------------------------------------------
// Kernel C: transpose g_outT[t][b] -> out[b][t]
// ---------------------------------------------------------------------------
__global__ void transpose_kernel(float* __restrict__ out) {
    __shared__ float tile[32][33];
    const int bBase = blockIdx.x * 32;
    const int tBase = blockIdx.y * 32;

    tile[threadIdx.y][threadIdx.x] =
        g_outT[(size_t)(tBase + threadIdx.y) * Bb + (bBase + threadIdx.x)];
    __syncthreads();
    out[(size_t)(bBase + threadIdx.y) * Tt + (tBase + threadIdx.x)] =
        tile[threadIdx.x][threadIdx.y];
}

// ---------------------------------------------------------------------------
extern "C" void kernel_launch(void* const* d_in, const int* in_sizes, int n_in,
                              void* d_out, int out_size) {
    const float* x       = (const float*)d_in[0];  // (B,T,8)
    const float* kern    = (const float*)d_in[1];  // (8,9)
    const float* rk      = (const float*)d_in[2];  // (3,9)
    const float* bias_i  = (const float*)d_in[3];  // (9,)
    const float* bias_r  = (const float*)d_in[4];  // (9,)
    const float* dense_w = (const float*)d_in[5];  // (3,1)
    const float* dense_b = (const float*)d_in[6];  // (1,)
    float* out = (float*)d_out;                    // (B,T,1)

    (void)in_sizes; (void)n_in; (void)out_size;

    dim3 gA(Bb / 256, Tt / 8);
    prep_kernel<<<gA, 256>>>(x, kern, bias_i, bias_r);

    scan_kernel<<<Bb / 32, 32>>>(rk, dense_w, dense_b);

    dim3 gC(Bb / 32, Tt / 32);
    transpose_kernel<<<gC, dim3(32, 32)>>>(out);
}